// round 2
// baseline (speedup 1.0000x reference)
#include <cuda_runtime.h>
#include <math.h>

#define NPTS   1000
#define BATCH  2
#define BNODES 2000
#define KNN    8
#define NEDGE  (BNODES*KNN)
#define NPAIR  499500   // NPTS*(NPTS-1)/2

// ---------------- scratch (static __device__; no allocations) ----------------
__device__ float g_sq[BNODES];
__device__ int   g_idx[NEDGE];
__device__ __align__(16) float g_U[BNODES*256];
__device__ __align__(16) float g_V[BNODES*256];
__device__ __align__(16) float g_H1[NEDGE*256];
__device__ __align__(16) float g_E[NEDGE*512];
__device__ __align__(16) float g_cat[BNODES*672];
__device__ __align__(16) float g_smh[BNODES*256];
__device__ __align__(16) float g_sf[BNODES*128];
__device__ __align__(16) float g_gmax[BATCH*128];
__device__ __align__(16) float g_hi[BNODES*128];
__device__ __align__(16) float g_hjg[BNODES*128];
__device__ __align__(16) float g_hg[BATCH*128];

// ---------------- squared norms ----------------
__global__ void sq_kernel(const float* __restrict__ x, int lda, int C) {
    int node = blockIdx.x;
    const float* xr = x + (size_t)node * lda;
    float s = 0.f;
    for (int c = threadIdx.x; c < C; c += 32) { float v = xr[c]; s += v * v; }
    #pragma unroll
    for (int o = 16; o; o >>= 1) s += __shfl_xor_sync(0xFFFFFFFFu, s, o);
    if (threadIdx.x == 0) g_sq[node] = s;
}

// ---------------- kNN: one block per node, iterative argmin (ties -> lowest idx) ----------------
__global__ void knn_kernel(const float* __restrict__ x, int lda, int C) {
    __shared__ float s_xi[128];
    __shared__ float s_d2[NPTS];
    __shared__ float s_rv[256];
    __shared__ int   s_ri[256];
    int node = blockIdx.x;
    int b    = node / NPTS;
    int base = b * NPTS;
    int tid  = threadIdx.x;

    for (int c = tid; c < C; c += 256) s_xi[c] = x[(size_t)node * lda + c];
    __syncthreads();

    float sqi = g_sq[node];
    for (int j = tid; j < NPTS; j += 256) {
        const float* xj = x + (size_t)(base + j) * lda;
        float dot = 0.f;
        #pragma unroll 4
        for (int c = 0; c < C; c++) dot += s_xi[c] * xj[c];
        s_d2[j] = sqi + g_sq[base + j] - 2.f * dot;
    }
    __syncthreads();

    for (int kk = 0; kk < KNN; kk++) {
        float bv = 3.3e38f; int bi = NPTS;
        for (int j = tid; j < NPTS; j += 256) {
            float v = s_d2[j];
            if (v < bv) { bv = v; bi = j; }   // strict <: within-thread ties keep lower j
        }
        s_rv[tid] = bv; s_ri[tid] = bi;
        __syncthreads();
        for (int s = 128; s > 0; s >>= 1) {
            if (tid < s) {
                float ov = s_rv[tid + s]; int oi = s_ri[tid + s];
                if (ov < s_rv[tid] || (ov == s_rv[tid] && oi < s_ri[tid])) {
                    s_rv[tid] = ov; s_ri[tid] = oi;
                }
            }
            __syncthreads();
        }
        if (tid == 0) {
            g_idx[node * KNN + kk] = base + s_ri[0];
            s_d2[s_ri[0]] = 3.3e38f;
        }
        __syncthreads();
    }
}

// ---------------- generic fp32 GEMM: C = A[M,K] @ (B - B2)[K,N] (+bias)(+relu) ----------------
__global__ void __launch_bounds__(256)
gemm_kernel(const float* __restrict__ A, int lda,
            const float* __restrict__ B, const float* __restrict__ B2, int ldb,
            float* __restrict__ C, int ldc,
            int M, int N, int K,
            const float* __restrict__ bias, int dorelu) {
    __shared__ __align__(16) float As[16][68];
    __shared__ __align__(16) float Bs[16][68];
    int tid = threadIdx.x;
    int tx = tid & 15, ty = tid >> 4;
    int m0 = blockIdx.x * 64, n0 = blockIdx.y * 64;
    float acc[4][4] = {};

    int la_m = tid >> 2;
    int la_k = (tid & 3) << 2;
    int lb_k = tid >> 4;
    int lb_n = (tid & 15) << 2;

    for (int k0 = 0; k0 < K; k0 += 16) {
        int am = m0 + la_m;
        #pragma unroll
        for (int q = 0; q < 4; q++) {
            int ak = k0 + la_k + q;
            As[la_k + q][la_m] = (am < M && ak < K) ? A[(size_t)am * lda + ak] : 0.f;
        }
        int bk = k0 + lb_k;
        #pragma unroll
        for (int q = 0; q < 4; q++) {
            int bn = n0 + lb_n + q;
            float v = 0.f;
            if (bk < K && bn < N) {
                size_t o = (size_t)bk * ldb + bn;
                v = B[o];
                if (B2) v -= B2[o];
            }
            Bs[lb_k][lb_n + q] = v;
        }
        __syncthreads();
        #pragma unroll
        for (int kk = 0; kk < 16; kk++) {
            float4 af = *(const float4*)&As[kk][ty << 2];
            float4 bf = *(const float4*)&Bs[kk][tx << 2];
            float a[4] = {af.x, af.y, af.z, af.w};
            float bb[4] = {bf.x, bf.y, bf.z, bf.w};
            #pragma unroll
            for (int r = 0; r < 4; r++)
                #pragma unroll
                for (int c = 0; c < 4; c++)
                    acc[r][c] += a[r] * bb[c];
        }
        __syncthreads();
    }

    #pragma unroll
    for (int r = 0; r < 4; r++) {
        int m = m0 + (ty << 2) + r;
        if (m >= M) continue;
        #pragma unroll
        for (int c = 0; c < 4; c++) {
            int n = n0 + (tx << 2) + c;
            if (n >= N) continue;
            float v = acc[r][c];
            if (bias) v += bias[n];
            if (dorelu) v = fmaxf(v, 0.f);
            C[(size_t)m * ldc + n] = v;
        }
    }
}

// ---------------- edge first-layer activations: H1[e][h] = relu(U[i]+V[j]+b1) ----------------
__global__ void edgeh_kernel(const float* __restrict__ U, const float* __restrict__ V,
                             const float* __restrict__ b1, int H, float* __restrict__ H1,
                             int total) {
    int idx = blockIdx.x * blockDim.x + threadIdx.x;
    if (idx >= total) return;
    int h = idx % H;
    int e = idx / H;
    int i = e >> 3;          // global node
    int j = g_idx[e];        // global node (includes batch base)
    float v = U[i * H + h] + V[j * H + h] + b1[h];
    H1[idx] = fmaxf(v, 0.f);
}

// ---------------- max over k neighbors ----------------
__global__ void maxk_kernel(const float* __restrict__ E, int H2,
                            float* __restrict__ out, int ldo, int total) {
    int idx = blockIdx.x * blockDim.x + threadIdx.x;
    if (idx >= total) return;
    int c = idx % H2;
    int node = idx / H2;
    const float* base = E + (size_t)node * KNN * H2 + c;
    float m = -3.3e38f;
    #pragma unroll
    for (int kk = 0; kk < KNN; kk++) m = fmaxf(m, base[kk * H2]);
    out[(size_t)node * ldo + c] = m;
}

// ---------------- global max pool over N ----------------
__global__ void gmax_kernel() {
    int b = blockIdx.x, c = threadIdx.x;
    const float* p = g_sf + (size_t)b * NPTS * 128 + c;
    float m = -3.3e38f;
    #pragma unroll 4
    for (int n = 0; n < NPTS; n++) m = fmaxf(m, p[n * 128]);
    g_gmax[b * 128 + c] = m;
}

// ---------------- hg = g @ ec_w1[256:384] + ec_b1 ----------------
__global__ void hg_kernel(const float* __restrict__ w1, const float* __restrict__ b1) {
    int b = blockIdx.x, c = threadIdx.x;
    float s = b1[c];
    #pragma unroll 4
    for (int d = 0; d < 128; d++) s += g_gmax[b * 128 + d] * w1[(256 + d) * 128 + c];
    g_hg[b * 128 + c] = s;
}

// ---------------- pair kernel: fused add+relu+dot(w2)+sigmoid over upper triangle ----------------
__global__ void __launch_bounds__(256)
pair_kernel(const float* __restrict__ w2, const float* __restrict__ b2,
            float* __restrict__ out) {
    int bx = blockIdx.x, by = blockIdx.y;
    if (bx < by) return;                 // only tiles that can contain j > i
    int b = blockIdx.z;
    __shared__ __align__(16) float s_hi[32][132];
    __shared__ __align__(16) float s_hj[32][132];
    __shared__ __align__(16) float s_w[128];

    int tid = threadIdx.y * 32 + threadIdx.x;
    int bi0 = by * 32, bj0 = bx * 32;

    for (int t = tid; t < 32 * 128; t += 256) {
        int r = t >> 7, c = t & 127;
        int gi = bi0 + r;
        s_hi[r][c] = (gi < NPTS) ? g_hi[(b * NPTS + gi) * 128 + c] : 0.f;
        int gj = bj0 + r;
        s_hj[r][c] = (gj < NPTS) ? g_hjg[(b * NPTS + gj) * 128 + c] + g_hg[b * 128 + c]
                                 : 0.f;
    }
    if (tid < 128) s_w[tid] = w2[tid];
    __syncthreads();

    float bias2 = b2[0];
    int tj = threadIdx.x;
    int gj = bj0 + tj;

    for (int ii = threadIdx.y; ii < 32; ii += 8) {
        int gi = bi0 + ii;
        if (gj < NPTS && gi < gj) {
            const float4* a4 = (const float4*)s_hi[ii];
            const float4* h4 = (const float4*)s_hj[tj];
            const float4* w4 = (const float4*)s_w;
            float acc0 = 0.f, acc1 = 0.f, acc2 = 0.f, acc3 = 0.f;
            #pragma unroll
            for (int c4 = 0; c4 < 32; c4++) {
                float4 a = a4[c4], h = h4[c4], w = w4[c4];
                acc0 += fmaxf(a.x + h.x, 0.f) * w.x;
                acc1 += fmaxf(a.y + h.y, 0.f) * w.y;
                acc2 += fmaxf(a.z + h.z, 0.f) * w.z;
                acc3 += fmaxf(a.w + h.w, 0.f) * w.w;
            }
            float m = (acc0 + acc1) + (acc2 + acc3) + bias2;
            int p = gi * (NPTS - 1) - (gi * (gi - 1)) / 2 + (gj - gi - 1);
            int off = b * NPAIR + p;
            out[off] = 1.f / (1.f + expf(-m));
            out[BATCH * NPAIR + off] = m;
        }
    }
}

// ============================ host side ============================
static void* sym_addr(const void* s) {
    void* p = nullptr;
    cudaGetSymbolAddress(&p, s);   // pure lookup, capture-safe
    return p;
}

static void gemm(const float* A, int lda, const float* B, const float* B2, int ldb,
                 float* C, int ldc, int M, int N, int K,
                 const float* bias, int dorelu) {
    dim3 g((M + 63) / 64, (N + 63) / 64);
    gemm_kernel<<<g, 256>>>(A, lda, B, B2, ldb, C, ldc, M, N, K, bias, dorelu);
}

static void edge_conv(const float* x, int lda, int C, int H, int H2,
                      const float* w1, const float* b1,
                      const float* w2, const float* b2,
                      float* U, float* V, float* H1, float* E,
                      float* outp, int ldo) {
    sq_kernel<<<BNODES, 32>>>(x, lda, C);
    knn_kernel<<<BNODES, 256>>>(x, lda, C);
    // U = x @ (w1[:C] - w1[C:]) ; V = x @ w1[C:]
    gemm(x, lda, w1, w1 + (size_t)C * H, H, U, H, BNODES, H, C, nullptr, 0);
    gemm(x, lda, w1 + (size_t)C * H, nullptr, H, V, H, BNODES, H, C, nullptr, 0);
    int tot = NEDGE * H;
    edgeh_kernel<<<(tot + 255) / 256, 256>>>(U, V, b1, H, H1, tot);
    gemm(H1, H, w2, nullptr, H2, E, H2, NEDGE, H2, H, b2, 0);
    int t2 = BNODES * H2;
    maxk_kernel<<<(t2 + 255) / 256, 256>>>(E, H2, outp, ldo, t2);
}

extern "C" void kernel_launch(void* const* d_in, const int* in_sizes, int n_in,
                              void* d_out, int out_size) {
    const float* in[21];
    for (int i = 0; i < 21; i++) in[i] = (const float*)d_in[i];
    const float* pos   = in[0];
    const float* c1_w1 = in[1];  const float* c1_b1 = in[2];
    const float* c1_w2 = in[3];  const float* c1_b2 = in[4];
    const float* c2_w1 = in[5];  const float* c2_b1 = in[6];
    const float* c2_w2 = in[7];  const float* c2_b2 = in[8];
    const float* c3_w1 = in[9];  const float* c3_b1 = in[10];
    const float* c3_w2 = in[11]; const float* c3_b2 = in[12];
    const float* sm_w1 = in[13]; const float* sm_b1 = in[14];
    const float* sm_w2 = in[15]; const float* sm_b2 = in[16];
    const float* ec_w1 = in[17]; const float* ec_b1 = in[18];
    const float* ec_w2 = in[19]; const float* ec_b2 = in[20];

    float* U   = (float*)sym_addr(g_U);
    float* V   = (float*)sym_addr(g_V);
    float* H1  = (float*)sym_addr(g_H1);
    float* E   = (float*)sym_addr(g_E);
    float* cat = (float*)sym_addr(g_cat);
    float* smh = (float*)sym_addr(g_smh);
    float* sf  = (float*)sym_addr(g_sf);
    float* hi  = (float*)sym_addr(g_hi);
    float* hjg = (float*)sym_addr(g_hjg);

    // conv1: pos[2000,3] -> x1 at cat+0 (32 ch)
    edge_conv(pos, 3, 3, 16, 32, c1_w1, c1_b1, c1_w2, c1_b2, U, V, H1, E, cat + 0, 672);
    // conv2: x1 -> x2 at cat+32 (128 ch)
    edge_conv(cat + 0, 672, 32, 64, 128, c2_w1, c2_b1, c2_w2, c2_b2, U, V, H1, E, cat + 32, 672);
    // conv3: x2 -> x3 at cat+160 (512 ch)
    edge_conv(cat + 32, 672, 128, 256, 512, c3_w1, c3_b1, c3_w2, c3_b2, U, V, H1, E, cat + 160, 672);

    // sm MLP: [2000,672] -> relu 256 -> 128
    gemm(cat, 672, sm_w1, nullptr, 256, smh, 256, BNODES, 256, 672, sm_b1, 1);
    gemm(smh, 256, sm_w2, nullptr, 128, sf, 128, BNODES, 128, 256, sm_b2, 0);

    // global max pool
    gmax_kernel<<<BATCH, 128>>>();

    // hi = sf @ ec_w1[:128]; hj = sf @ ec_w1[128:256]
    gemm(sf, 128, ec_w1, nullptr, 128, hi, 128, BNODES, 128, 128, nullptr, 0);
    gemm(sf, 128, ec_w1 + 128 * 128, nullptr, 128, hjg, 128, BNODES, 128, 128, nullptr, 0);
    // hg = g @ ec_w1[256:] + ec_b1
    hg_kernel<<<BATCH, 128>>>(ec_w1, ec_b1);

    // fused pair stage -> d_out = [pair_prob (B*P), mlp_out (B*P)]
    pair_kernel<<<dim3(32, 32, BATCH), dim3(32, 8)>>>(ec_w2, ec_b2, (float*)d_out);
}

// round 3
// speedup vs baseline: 3.4616x; 3.4616x over previous
#include <cuda_runtime.h>
#include <math.h>

#define NPTS   1000
#define BATCH  2
#define BNODES 2000
#define KNN    8
#define NEDGE  (BNODES*KNN)
#define NPAIR  499500   // NPTS*(NPTS-1)/2

// ---------------- scratch (static __device__; no allocations) ----------------
__device__ float g_sq[BNODES];
__device__ int   g_idx[NEDGE];
__device__ __align__(16) float g_U[BNODES*256];
__device__ __align__(16) float g_V[BNODES*256];
__device__ __align__(16) float g_G[BATCH*NPTS*NPTS];   // per-batch dot matrix
__device__ __align__(16) float g_cat[BNODES*672];
__device__ __align__(16) float g_smh[BNODES*256];
__device__ __align__(16) float g_sf[BNODES*128];
__device__ __align__(16) float g_gmax[BATCH*128];
__device__ __align__(16) float g_hi[BNODES*128];
__device__ __align__(16) float g_hjg[BNODES*128];
__device__ __align__(16) float g_hg[BATCH*128];

// ---------------- squared norms ----------------
__global__ void sq_kernel(const float* __restrict__ x, int lda, int C) {
    int node = blockIdx.x;
    const float* xr = x + (size_t)node * lda;
    float s = 0.f;
    for (int c = threadIdx.x; c < C; c += 32) { float v = xr[c]; s += v * v; }
    #pragma unroll
    for (int o = 16; o; o >>= 1) s += __shfl_xor_sync(0xFFFFFFFFu, s, o);
    if (threadIdx.x == 0) g_sq[node] = s;
}

// ---------------- X @ X^T per batch: 128x128 tile, 8x8 per thread ----------------
__global__ void __launch_bounds__(256)
xxt_kernel(const float* __restrict__ x, int lda, int C, float* __restrict__ G) {
    __shared__ __align__(16) float As[16][132];
    __shared__ __align__(16) float Bs[16][132];
    int b  = blockIdx.z;
    int m0 = blockIdx.y * 128, n0 = blockIdx.x * 128;
    const float* xb = x + (size_t)b * NPTS * lda;
    int tid  = threadIdx.x;
    int lrow = tid >> 1, lk8 = (tid & 1) * 8;
    int tx = tid & 15, ty = tid >> 4;
    float acc[8][8] = {};

    int ar = m0 + lrow, br = n0 + lrow;
    for (int k0 = 0; k0 < C; k0 += 16) {
        #pragma unroll
        for (int q = 0; q < 8; q++) {
            int k = k0 + lk8 + q;
            As[lk8 + q][lrow] = (ar < NPTS && k < C) ? xb[(size_t)ar * lda + k] : 0.f;
            Bs[lk8 + q][lrow] = (br < NPTS && k < C) ? xb[(size_t)br * lda + k] : 0.f;
        }
        __syncthreads();
        #pragma unroll
        for (int kk = 0; kk < 16; kk++) {
            float a[8], bb[8];
            *(float4*)&a[0]  = *(const float4*)&As[kk][ty * 8];
            *(float4*)&a[4]  = *(const float4*)&As[kk][ty * 8 + 4];
            *(float4*)&bb[0] = *(const float4*)&Bs[kk][tx * 8];
            *(float4*)&bb[4] = *(const float4*)&Bs[kk][tx * 8 + 4];
            #pragma unroll
            for (int r = 0; r < 8; r++)
                #pragma unroll
                for (int c = 0; c < 8; c++)
                    acc[r][c] += a[r] * bb[c];
        }
        __syncthreads();
    }
    #pragma unroll
    for (int r = 0; r < 8; r++) {
        int i = m0 + ty * 8 + r;
        if (i >= NPTS) continue;
        #pragma unroll
        for (int c = 0; c < 8; c++) {
            int j = n0 + tx * 8 + c;
            if (j < NPTS)
                G[((size_t)b * NPTS + i) * NPTS + j] = acc[r][c];
        }
    }
}

// ---------------- top-8 per node from dot matrix (ties -> lowest idx) ----------------
__global__ void topk_kernel(const float* __restrict__ G) {
    __shared__ float d2[NPTS];
    __shared__ float rv[128];
    __shared__ int   ri[128];
    int node = blockIdx.x;
    int b = node / NPTS, i = node - b * NPTS, base = b * NPTS;
    int tid = threadIdx.x;
    float sqi = g_sq[node];
    const float* Grow = G + ((size_t)b * NPTS + i) * NPTS;
    for (int j = tid; j < NPTS; j += 128)
        d2[j] = sqi + g_sq[base + j] - 2.f * Grow[j];
    __syncthreads();
    for (int kk = 0; kk < KNN; kk++) {
        float bv = 3.3e38f; int bi = NPTS;
        for (int j = tid; j < NPTS; j += 128) {
            float v = d2[j];
            if (v < bv) { bv = v; bi = j; }
        }
        rv[tid] = bv; ri[tid] = bi;
        __syncthreads();
        for (int s = 64; s > 0; s >>= 1) {
            if (tid < s) {
                float ov = rv[tid + s]; int oi = ri[tid + s];
                if (ov < rv[tid] || (ov == rv[tid] && oi < ri[tid])) {
                    rv[tid] = ov; ri[tid] = oi;
                }
            }
            __syncthreads();
        }
        if (tid == 0) {
            g_idx[node * KNN + kk] = base + ri[0];
            d2[ri[0]] = 3.3e38f;
        }
        __syncthreads();
    }
}

// ---------------- fused edge GEMM: A=relu(U[i]+V[j]+b1) on the fly, max-over-k epilogue ----
// out[node][n] = max_{kk<8} ( relu(U[i]+V[j]+b1) @ W2 )[edge][n] + b2[n]
__global__ void __launch_bounds__(256)
fused_edge_gemm(const float* __restrict__ U, const float* __restrict__ V,
                const float* __restrict__ b1, const float* __restrict__ W2,
                const float* __restrict__ b2, float* __restrict__ out,
                int ldo, int H, int H2) {
    __shared__ __align__(16) float As[16][132];
    __shared__ __align__(16) float Bs[16][132];
    int tid = threadIdx.x;
    int m0 = blockIdx.x * 128, n0 = blockIdx.y * 128;
    int tx = tid & 15, ty = tid >> 4;
    float acc[8][8] = {};

    // A-fill mapping: row = tid>>1 (0..127), 8 k's at (tid&1)*8
    int arow = tid >> 1, ak8 = (tid & 1) * 8;
    int e = m0 + arow;
    const float* Urow = U + (size_t)(e >> 3) * H;
    const float* Vrow = V + (size_t)g_idx[e] * H;
    // B-fill mapping: k = tid>>4 (0..15), 8 n's at (tid&15)*8
    int bk = tid >> 4, bn8 = (tid & 15) * 8;

    for (int k0 = 0; k0 < H; k0 += 16) {
        // A tile (always full: H multiple of 16, rows always valid)
        {
            float4 u0 = *(const float4*)&Urow[k0 + ak8];
            float4 u1 = *(const float4*)&Urow[k0 + ak8 + 4];
            float4 v0 = *(const float4*)&Vrow[k0 + ak8];
            float4 v1 = *(const float4*)&Vrow[k0 + ak8 + 4];
            float4 c0 = *(const float4*)&b1[k0 + ak8];
            float4 c1 = *(const float4*)&b1[k0 + ak8 + 4];
            As[ak8 + 0][arow] = fmaxf(u0.x + v0.x + c0.x, 0.f);
            As[ak8 + 1][arow] = fmaxf(u0.y + v0.y + c0.y, 0.f);
            As[ak8 + 2][arow] = fmaxf(u0.z + v0.z + c0.z, 0.f);
            As[ak8 + 3][arow] = fmaxf(u0.w + v0.w + c0.w, 0.f);
            As[ak8 + 4][arow] = fmaxf(u1.x + v1.x + c1.x, 0.f);
            As[ak8 + 5][arow] = fmaxf(u1.y + v1.y + c1.y, 0.f);
            As[ak8 + 6][arow] = fmaxf(u1.z + v1.z + c1.z, 0.f);
            As[ak8 + 7][arow] = fmaxf(u1.w + v1.w + c1.w, 0.f);
        }
        // B tile
        if (n0 + bn8 + 7 < H2) {
            float4 w0 = *(const float4*)&W2[(size_t)(k0 + bk) * H2 + n0 + bn8];
            float4 w1 = *(const float4*)&W2[(size_t)(k0 + bk) * H2 + n0 + bn8 + 4];
            Bs[bk][bn8 + 0] = w0.x; Bs[bk][bn8 + 1] = w0.y;
            Bs[bk][bn8 + 2] = w0.z; Bs[bk][bn8 + 3] = w0.w;
            Bs[bk][bn8 + 4] = w1.x; Bs[bk][bn8 + 5] = w1.y;
            Bs[bk][bn8 + 6] = w1.z; Bs[bk][bn8 + 7] = w1.w;
        } else {
            #pragma unroll
            for (int q = 0; q < 8; q++) {
                int n = n0 + bn8 + q;
                Bs[bk][bn8 + q] = (n < H2) ? W2[(size_t)(k0 + bk) * H2 + n] : 0.f;
            }
        }
        __syncthreads();
        #pragma unroll
        for (int kk = 0; kk < 16; kk++) {
            float a[8], bb[8];
            *(float4*)&a[0]  = *(const float4*)&As[kk][ty * 8];
            *(float4*)&a[4]  = *(const float4*)&As[kk][ty * 8 + 4];
            *(float4*)&bb[0] = *(const float4*)&Bs[kk][tx * 8];
            *(float4*)&bb[4] = *(const float4*)&Bs[kk][tx * 8 + 4];
            #pragma unroll
            for (int r = 0; r < 8; r++)
                #pragma unroll
                for (int c = 0; c < 8; c++)
                    acc[r][c] += a[r] * bb[c];
        }
        __syncthreads();
    }

    // epilogue: rows ty*8..ty*8+7 are exactly the 8 edges of one node
    int node = (m0 >> 3) + ty;
    #pragma unroll
    for (int c = 0; c < 8; c++) {
        int n = n0 + tx * 8 + c;
        if (n >= H2) continue;
        float m = acc[0][c];
        #pragma unroll
        for (int r = 1; r < 8; r++) m = fmaxf(m, acc[r][c]);
        out[(size_t)node * ldo + n] = m + b2[n];
    }
}

// ---------------- generic fp32 GEMM (64x64, 4x4): C = A @ (B - B2) (+bias)(+relu) -------
__global__ void __launch_bounds__(256)
gemm_kernel(const float* __restrict__ A, int lda,
            const float* __restrict__ B, const float* __restrict__ B2, int ldb,
            float* __restrict__ C, int ldc,
            int M, int N, int K,
            const float* __restrict__ bias, int dorelu) {
    __shared__ __align__(16) float As[16][68];
    __shared__ __align__(16) float Bs[16][68];
    int tid = threadIdx.x;
    int tx = tid & 15, ty = tid >> 4;
    int m0 = blockIdx.x * 64, n0 = blockIdx.y * 64;
    float acc[4][4] = {};

    int la_m = tid >> 2;
    int la_k = (tid & 3) << 2;
    int lb_k = tid >> 4;
    int lb_n = (tid & 15) << 2;

    for (int k0 = 0; k0 < K; k0 += 16) {
        int am = m0 + la_m;
        #pragma unroll
        for (int q = 0; q < 4; q++) {
            int ak = k0 + la_k + q;
            As[la_k + q][la_m] = (am < M && ak < K) ? A[(size_t)am * lda + ak] : 0.f;
        }
        int bk = k0 + lb_k;
        #pragma unroll
        for (int q = 0; q < 4; q++) {
            int bn = n0 + lb_n + q;
            float v = 0.f;
            if (bk < K && bn < N) {
                size_t o = (size_t)bk * ldb + bn;
                v = B[o];
                if (B2) v -= B2[o];
            }
            Bs[lb_k][lb_n + q] = v;
        }
        __syncthreads();
        #pragma unroll
        for (int kk = 0; kk < 16; kk++) {
            float4 af = *(const float4*)&As[kk][ty << 2];
            float4 bf = *(const float4*)&Bs[kk][tx << 2];
            float a[4] = {af.x, af.y, af.z, af.w};
            float bb[4] = {bf.x, bf.y, bf.z, bf.w};
            #pragma unroll
            for (int r = 0; r < 4; r++)
                #pragma unroll
                for (int c = 0; c < 4; c++)
                    acc[r][c] += a[r] * bb[c];
        }
        __syncthreads();
    }

    #pragma unroll
    for (int r = 0; r < 4; r++) {
        int m = m0 + (ty << 2) + r;
        if (m >= M) continue;
        #pragma unroll
        for (int c = 0; c < 4; c++) {
            int n = n0 + (tx << 2) + c;
            if (n >= N) continue;
            float v = acc[r][c];
            if (bias) v += bias[n];
            if (dorelu) v = fmaxf(v, 0.f);
            C[(size_t)m * ldc + n] = v;
        }
    }
}

// ---------------- global max pool over N ----------------
__global__ void gmax_kernel() {
    int b = blockIdx.x, c = threadIdx.x;
    const float* p = g_sf + (size_t)b * NPTS * 128 + c;
    float m = -3.3e38f;
    #pragma unroll 4
    for (int n = 0; n < NPTS; n++) m = fmaxf(m, p[n * 128]);
    g_gmax[b * 128 + c] = m;
}

// ---------------- hg = g @ ec_w1[256:384] + ec_b1 ----------------
__global__ void hg_kernel(const float* __restrict__ w1, const float* __restrict__ b1) {
    int b = blockIdx.x, c = threadIdx.x;
    float s = b1[c];
    #pragma unroll 4
    for (int d = 0; d < 128; d++) s += g_gmax[b * 128 + d] * w1[(256 + d) * 128 + c];
    g_hg[b * 128 + c] = s;
}

// ---------------- pair kernel: 64x64 tile, 4x4 pairs/thread, fused relu+dot+sigmoid ----
__global__ void __launch_bounds__(256)
pair_kernel(const float* __restrict__ w2, const float* __restrict__ b2,
            float* __restrict__ out) {
    int bx = blockIdx.x, by = blockIdx.y;   // bx = j tile, by = i tile
    if (bx < by) return;
    int b = blockIdx.z;
    extern __shared__ float ps[];
    float* s_hi = ps;                 // 64 x 132
    float* s_hj = ps + 64 * 132;      // 64 x 132
    float* s_w  = ps + 2 * 64 * 132;  // 128

    int tid = threadIdx.y * 16 + threadIdx.x;
    int bi0 = by * 64, bj0 = bx * 64;

    for (int t = tid; t < 64 * 32; t += 256) {
        int r = t >> 5, c4 = (t & 31) << 2;
        int gi = bi0 + r;
        float4 v = make_float4(0.f, 0.f, 0.f, 0.f);
        if (gi < NPTS) v = *(const float4*)&g_hi[((size_t)(b * NPTS + gi)) * 128 + c4];
        *(float4*)&s_hi[r * 132 + c4] = v;
        int gj = bj0 + r;
        float4 u = make_float4(0.f, 0.f, 0.f, 0.f);
        if (gj < NPTS) {
            u = *(const float4*)&g_hjg[((size_t)(b * NPTS + gj)) * 128 + c4];
            float4 hgv = *(const float4*)&g_hg[b * 128 + c4];
            u.x += hgv.x; u.y += hgv.y; u.z += hgv.z; u.w += hgv.w;
        }
        *(float4*)&s_hj[r * 132 + c4] = u;
    }
    if (tid < 32) *(float4*)&s_w[tid * 4] = *(const float4*)&w2[tid * 4];
    __syncthreads();

    int ri0 = threadIdx.y * 4, cj0 = threadIdx.x * 4;
    float acc[4][4] = {};
    for (int c4 = 0; c4 < 128; c4 += 4) {
        float4 w = *(const float4*)&s_w[c4];
        float4 A[4], H[4];
        #pragma unroll
        for (int r = 0; r < 4; r++) A[r] = *(const float4*)&s_hi[(ri0 + r) * 132 + c4];
        #pragma unroll
        for (int c = 0; c < 4; c++) H[c] = *(const float4*)&s_hj[(cj0 + c) * 132 + c4];
        #pragma unroll
        for (int r = 0; r < 4; r++)
            #pragma unroll
            for (int c = 0; c < 4; c++) {
                acc[r][c] += fmaxf(A[r].x + H[c].x, 0.f) * w.x
                           + fmaxf(A[r].y + H[c].y, 0.f) * w.y
                           + fmaxf(A[r].z + H[c].z, 0.f) * w.z
                           + fmaxf(A[r].w + H[c].w, 0.f) * w.w;
            }
    }

    float bias2 = b2[0];
    #pragma unroll
    for (int r = 0; r < 4; r++) {
        int gi = bi0 + ri0 + r;
        #pragma unroll
        for (int c = 0; c < 4; c++) {
            int gj = bj0 + cj0 + c;
            if (gj < NPTS && gi < gj) {
                float m = acc[r][c] + bias2;
                int p = gi * (NPTS - 1) - (gi * (gi - 1)) / 2 + (gj - gi - 1);
                int off = b * NPAIR + p;
                out[off] = 1.f / (1.f + __expf(-m));
                out[BATCH * NPAIR + off] = m;
            }
        }
    }
}

// ============================ host side ============================
static void* sym_addr(const void* s) {
    void* p = nullptr;
    cudaGetSymbolAddress(&p, s);
    return p;
}

static void gemm(const float* A, int lda, const float* B, const float* B2, int ldb,
                 float* C, int ldc, int M, int N, int K,
                 const float* bias, int dorelu) {
    dim3 g((M + 63) / 64, (N + 63) / 64);
    gemm_kernel<<<g, 256>>>(A, lda, B, B2, ldb, C, ldc, M, N, K, bias, dorelu);
}

static void edge_conv(const float* x, int lda, int C, int H, int H2,
                      const float* w1, const float* b1,
                      const float* w2, const float* b2,
                      float* U, float* V, float* G,
                      float* outp, int ldo) {
    sq_kernel<<<BNODES, 32>>>(x, lda, C);
    xxt_kernel<<<dim3(8, 8, BATCH), 256>>>(x, lda, C, G);
    topk_kernel<<<BNODES, 128>>>(G);
    // U = x @ (w1[:C] - w1[C:]) ; V = x @ w1[C:]
    gemm(x, lda, w1, w1 + (size_t)C * H, H, U, H, BNODES, H, C, nullptr, 0);
    gemm(x, lda, w1 + (size_t)C * H, nullptr, H, V, H, BNODES, H, C, nullptr, 0);
    fused_edge_gemm<<<dim3(125, (H2 + 127) / 128), 256>>>(U, V, b1, w2, b2, outp, ldo, H, H2);
}

extern "C" void kernel_launch(void* const* d_in, const int* in_sizes, int n_in,
                              void* d_out, int out_size) {
    const float* in[21];
    for (int i = 0; i < 21; i++) in[i] = (const float*)d_in[i];
    const float* pos   = in[0];
    const float* c1_w1 = in[1];  const float* c1_b1 = in[2];
    const float* c1_w2 = in[3];  const float* c1_b2 = in[4];
    const float* c2_w1 = in[5];  const float* c2_b1 = in[6];
    const float* c2_w2 = in[7];  const float* c2_b2 = in[8];
    const float* c3_w1 = in[9];  const float* c3_b1 = in[10];
    const float* c3_w2 = in[11]; const float* c3_b2 = in[12];
    const float* sm_w1 = in[13]; const float* sm_b1 = in[14];
    const float* sm_w2 = in[15]; const float* sm_b2 = in[16];
    const float* ec_w1 = in[17]; const float* ec_b1 = in[18];
    const float* ec_w2 = in[19]; const float* ec_b2 = in[20];

    float* U   = (float*)sym_addr(g_U);
    float* V   = (float*)sym_addr(g_V);
    float* G   = (float*)sym_addr(g_G);
    float* cat = (float*)sym_addr(g_cat);
    float* smh = (float*)sym_addr(g_smh);
    float* sf  = (float*)sym_addr(g_sf);
    float* hi  = (float*)sym_addr(g_hi);
    float* hjg = (float*)sym_addr(g_hjg);

    // conv1: pos[2000,3] -> x1 at cat+0 (32 ch)
    edge_conv(pos, 3, 3, 16, 32, c1_w1, c1_b1, c1_w2, c1_b2, U, V, G, cat + 0, 672);
    // conv2: x1 -> x2 at cat+32 (128 ch)
    edge_conv(cat + 0, 672, 32, 64, 128, c2_w1, c2_b1, c2_w2, c2_b2, U, V, G, cat + 32, 672);
    // conv3: x2 -> x3 at cat+160 (512 ch)
    edge_conv(cat + 32, 672, 128, 256, 512, c3_w1, c3_b1, c3_w2, c3_b2, U, V, G, cat + 160, 672);

    // sm MLP: [2000,672] -> relu 256 -> 128
    gemm(cat, 672, sm_w1, nullptr, 256, smh, 256, BNODES, 256, 672, sm_b1, 1);
    gemm(smh, 256, sm_w2, nullptr, 128, sf, 128, BNODES, 128, 256, sm_b2, 0);

    // global max pool
    gmax_kernel<<<BATCH, 128>>>();

    // hi = sf @ ec_w1[:128]; hj = sf @ ec_w1[128:256]
    gemm(sf, 128, ec_w1, nullptr, 128, hi, 128, BNODES, 128, 128, nullptr, 0);
    gemm(sf, 128, ec_w1 + 128 * 128, nullptr, 128, hjg, 128, BNODES, 128, 128, nullptr, 0);
    // hg = g @ ec_w1[256:] + ec_b1
    hg_kernel<<<BATCH, 128>>>(ec_w1, ec_b1);

    // fused pair stage -> d_out = [pair_prob (B*P), mlp_out (B*P)]
    size_t psmem = (2 * 64 * 132 + 128) * sizeof(float);
    cudaFuncSetAttribute(pair_kernel, cudaFuncAttributeMaxDynamicSharedMemorySize, (int)psmem);
    pair_kernel<<<dim3(16, 16, BATCH), dim3(16, 16), psmem>>>(ec_w2, ec_b2, (float*)d_out);
}

// round 4
// speedup vs baseline: 3.6296x; 1.0485x over previous
#include <cuda_runtime.h>
#include <math.h>

#define NPTS   1000
#define BATCH  2
#define BNODES 2000
#define KNN    8
#define NEDGE  (BNODES*KNN)
#define NPAIR  499500   // NPTS*(NPTS-1)/2

typedef unsigned long long ull;

// packed f32x2 helpers (Blackwell: fma.rn.f32x2 — PTX-only, ptxas won't emit it)
__device__ __forceinline__ ull pk2(float x) {
    ull r; asm("mov.b64 %0, {%1, %1};" : "=l"(r) : "f"(x)); return r;
}
__device__ __forceinline__ void fma2(ull& d, ull a, ull b) {
    asm("fma.rn.f32x2 %0, %1, %2, %0;" : "+l"(d) : "l"(a), "l"(b));
}
__device__ __forceinline__ void unpk(ull v, float& lo, float& hi) {
    asm("mov.b64 {%0, %1}, %2;" : "=f"(lo), "=f"(hi) : "l"(v));
}

// ---------------- scratch (static __device__; no allocations) ----------------
__device__ float g_sq[BNODES];
__device__ int   g_idx[NEDGE];
__device__ __align__(16) float g_U[BNODES*256];
__device__ __align__(16) float g_V[BNODES*256];
__device__ __align__(16) float g_G[BATCH*NPTS*NPTS];   // per-batch dot matrix
__device__ __align__(16) float g_cat[BNODES*672];
__device__ __align__(16) float g_smh[BNODES*256];
__device__ __align__(16) float g_sf[BNODES*128];
__device__ __align__(16) float g_gmax[BATCH*128];
__device__ __align__(16) float g_hi[BNODES*128];
__device__ __align__(16) float g_hjg[BNODES*128];
__device__ __align__(16) float g_hg[BATCH*128];

// ---------------- X @ X^T per batch: 128x128 tile, 8x8 per thread, f32x2 ----------------
__global__ void __launch_bounds__(256)
xxt_kernel(const float* __restrict__ x, int lda, int C, float* __restrict__ G) {
    __shared__ __align__(16) float As[16][132];
    __shared__ __align__(16) float Bs[16][132];
    int b  = blockIdx.z;
    int m0 = blockIdx.y * 128, n0 = blockIdx.x * 128;
    const float* xb = x + (size_t)b * NPTS * lda;
    int tid  = threadIdx.x;
    int lrow = tid >> 1, lk8 = (tid & 1) * 8;
    int tx = tid & 15, ty = tid >> 4;
    ull acc2[8][4];
    #pragma unroll
    for (int r = 0; r < 8; r++)
        #pragma unroll
        for (int q = 0; q < 4; q++) acc2[r][q] = 0ull;

    int ar = m0 + lrow, br = n0 + lrow;
    for (int k0 = 0; k0 < C; k0 += 16) {
        #pragma unroll
        for (int q = 0; q < 8; q++) {
            int k = k0 + lk8 + q;
            As[lk8 + q][lrow] = (ar < NPTS && k < C) ? xb[(size_t)ar * lda + k] : 0.f;
            Bs[lk8 + q][lrow] = (br < NPTS && k < C) ? xb[(size_t)br * lda + k] : 0.f;
        }
        __syncthreads();
        #pragma unroll
        for (int kk = 0; kk < 16; kk++) {
            float a[8];
            *(float4*)&a[0] = *(const float4*)&As[kk][ty * 8];
            *(float4*)&a[4] = *(const float4*)&As[kk][ty * 8 + 4];
            ull bp[4];
            {
                ulonglong2 t0 = *(const ulonglong2*)&Bs[kk][tx * 8];
                ulonglong2 t1 = *(const ulonglong2*)&Bs[kk][tx * 8 + 4];
                bp[0] = t0.x; bp[1] = t0.y; bp[2] = t1.x; bp[3] = t1.y;
            }
            #pragma unroll
            for (int r = 0; r < 8; r++) {
                ull ap = pk2(a[r]);
                #pragma unroll
                for (int q = 0; q < 4; q++) fma2(acc2[r][q], ap, bp[q]);
            }
        }
        __syncthreads();
    }
    #pragma unroll
    for (int r = 0; r < 8; r++) {
        int i = m0 + ty * 8 + r;
        if (i >= NPTS) continue;
        float av[8];
        #pragma unroll
        for (int q = 0; q < 4; q++) unpk(acc2[r][q], av[2 * q], av[2 * q + 1]);
        #pragma unroll
        for (int c = 0; c < 8; c++) {
            int j = n0 + tx * 8 + c;
            if (j < NPTS)
                G[((size_t)b * NPTS + i) * NPTS + j] = av[c];
        }
    }
}

// ---------------- diag of G -> squared norms ----------------
__global__ void diag_kernel(const float* __restrict__ G) {
    int n = blockIdx.x * 256 + threadIdx.x;
    if (n < BNODES) {
        int b = n / NPTS, i = n - b * NPTS;
        g_sq[n] = G[((size_t)b * NPTS + i) * NPTS + i];
    }
}

// ---------------- top-8 per node from dot matrix (ties -> lowest idx) ----------------
__global__ void topk_kernel(const float* __restrict__ G) {
    __shared__ float d2[NPTS];
    __shared__ float rv[128];
    __shared__ int   ri[128];
    int node = blockIdx.x;
    int b = node / NPTS, i = node - b * NPTS, base = b * NPTS;
    int tid = threadIdx.x;
    float sqi = g_sq[node];
    const float* Grow = G + ((size_t)b * NPTS + i) * NPTS;
    for (int j = tid; j < NPTS; j += 128)
        d2[j] = sqi + g_sq[base + j] - 2.f * Grow[j];
    __syncthreads();
    for (int kk = 0; kk < KNN; kk++) {
        float bv = 3.3e38f; int bi = NPTS;
        for (int j = tid; j < NPTS; j += 128) {
            float v = d2[j];
            if (v < bv) { bv = v; bi = j; }
        }
        rv[tid] = bv; ri[tid] = bi;
        __syncthreads();
        for (int s = 64; s > 0; s >>= 1) {
            if (tid < s) {
                float ov = rv[tid + s]; int oi = ri[tid + s];
                if (ov < rv[tid] || (ov == rv[tid] && oi < ri[tid])) {
                    rv[tid] = ov; ri[tid] = oi;
                }
            }
            __syncthreads();
        }
        if (tid == 0) {
            g_idx[node * KNN + kk] = base + ri[0];
            d2[ri[0]] = 3.3e38f;
        }
        __syncthreads();
    }
}

// ---------------- fused edge GEMM: A=relu(U[i]+V[j]+b1) on the fly, max-over-k epilogue ----
__global__ void __launch_bounds__(256)
fused_edge_gemm(const float* __restrict__ U, const float* __restrict__ V,
                const float* __restrict__ b1, const float* __restrict__ W2,
                const float* __restrict__ b2, float* __restrict__ out,
                int ldo, int H, int H2) {
    __shared__ __align__(16) float As[16][132];
    __shared__ __align__(16) float Bs[16][132];
    int tid = threadIdx.x;
    int m0 = blockIdx.x * 128, n0 = blockIdx.y * 128;
    int tx = tid & 15, ty = tid >> 4;
    ull acc2[8][4];
    #pragma unroll
    for (int r = 0; r < 8; r++)
        #pragma unroll
        for (int q = 0; q < 4; q++) acc2[r][q] = 0ull;

    int arow = tid >> 1, ak8 = (tid & 1) * 8;
    int e = m0 + arow;
    const float* Urow = U + (size_t)(e >> 3) * H;
    const float* Vrow = V + (size_t)g_idx[e] * H;
    int bk = tid >> 4, bn8 = (tid & 15) * 8;

    for (int k0 = 0; k0 < H; k0 += 16) {
        {
            float4 u0 = *(const float4*)&Urow[k0 + ak8];
            float4 u1 = *(const float4*)&Urow[k0 + ak8 + 4];
            float4 v0 = *(const float4*)&Vrow[k0 + ak8];
            float4 v1 = *(const float4*)&Vrow[k0 + ak8 + 4];
            float4 c0 = *(const float4*)&b1[k0 + ak8];
            float4 c1 = *(const float4*)&b1[k0 + ak8 + 4];
            As[ak8 + 0][arow] = fmaxf(u0.x + v0.x + c0.x, 0.f);
            As[ak8 + 1][arow] = fmaxf(u0.y + v0.y + c0.y, 0.f);
            As[ak8 + 2][arow] = fmaxf(u0.z + v0.z + c0.z, 0.f);
            As[ak8 + 3][arow] = fmaxf(u0.w + v0.w + c0.w, 0.f);
            As[ak8 + 4][arow] = fmaxf(u1.x + v1.x + c1.x, 0.f);
            As[ak8 + 5][arow] = fmaxf(u1.y + v1.y + c1.y, 0.f);
            As[ak8 + 6][arow] = fmaxf(u1.z + v1.z + c1.z, 0.f);
            As[ak8 + 7][arow] = fmaxf(u1.w + v1.w + c1.w, 0.f);
        }
        if (n0 + bn8 + 7 < H2) {
            float4 w0 = *(const float4*)&W2[(size_t)(k0 + bk) * H2 + n0 + bn8];
            float4 w1 = *(const float4*)&W2[(size_t)(k0 + bk) * H2 + n0 + bn8 + 4];
            Bs[bk][bn8 + 0] = w0.x; Bs[bk][bn8 + 1] = w0.y;
            Bs[bk][bn8 + 2] = w0.z; Bs[bk][bn8 + 3] = w0.w;
            Bs[bk][bn8 + 4] = w1.x; Bs[bk][bn8 + 5] = w1.y;
            Bs[bk][bn8 + 6] = w1.z; Bs[bk][bn8 + 7] = w1.w;
        } else {
            #pragma unroll
            for (int q = 0; q < 8; q++) {
                int n = n0 + bn8 + q;
                Bs[bk][bn8 + q] = (n < H2) ? W2[(size_t)(k0 + bk) * H2 + n] : 0.f;
            }
        }
        __syncthreads();
        #pragma unroll
        for (int kk = 0; kk < 16; kk++) {
            float a[8];
            *(float4*)&a[0] = *(const float4*)&As[kk][ty * 8];
            *(float4*)&a[4] = *(const float4*)&As[kk][ty * 8 + 4];
            ull bp[4];
            {
                ulonglong2 t0 = *(const ulonglong2*)&Bs[kk][tx * 8];
                ulonglong2 t1 = *(const ulonglong2*)&Bs[kk][tx * 8 + 4];
                bp[0] = t0.x; bp[1] = t0.y; bp[2] = t1.x; bp[3] = t1.y;
            }
            #pragma unroll
            for (int r = 0; r < 8; r++) {
                ull ap = pk2(a[r]);
                #pragma unroll
                for (int q = 0; q < 4; q++) fma2(acc2[r][q], ap, bp[q]);
            }
        }
        __syncthreads();
    }

    // epilogue: rows ty*8..ty*8+7 are exactly the 8 edges of one node
    int node = (m0 >> 3) + ty;
    float av[8][8];
    #pragma unroll
    for (int r = 0; r < 8; r++)
        #pragma unroll
        for (int q = 0; q < 4; q++) unpk(acc2[r][q], av[r][2 * q], av[r][2 * q + 1]);
    #pragma unroll
    for (int c = 0; c < 8; c++) {
        int n = n0 + tx * 8 + c;
        if (n >= H2) continue;
        float m = av[0][c];
        #pragma unroll
        for (int r = 1; r < 8; r++) m = fmaxf(m, av[r][c]);
        out[(size_t)node * ldo + n] = m + b2[n];
    }
}

// ---------------- generic fp32 GEMM (64x64, 4x4, f32x2): C = A @ B (+bias)(+relu) -------
__global__ void __launch_bounds__(256)
gemm_kernel(const float* __restrict__ A, int lda,
            const float* __restrict__ B, int ldb,
            float* __restrict__ C, int ldc,
            int M, int N, int K,
            const float* __restrict__ bias, int dorelu) {
    __shared__ __align__(16) float As[16][68];
    __shared__ __align__(16) float Bs[16][68];
    int tid = threadIdx.x;
    int tx = tid & 15, ty = tid >> 4;
    int m0 = blockIdx.x * 64, n0 = blockIdx.y * 64;
    ull acc2[4][2];
    #pragma unroll
    for (int r = 0; r < 4; r++) { acc2[r][0] = 0ull; acc2[r][1] = 0ull; }

    int la_m = tid >> 2;
    int la_k = (tid & 3) << 2;
    int lb_k = tid >> 4;
    int lb_n = (tid & 15) << 2;

    for (int k0 = 0; k0 < K; k0 += 16) {
        int am = m0 + la_m;
        #pragma unroll
        for (int q = 0; q < 4; q++) {
            int ak = k0 + la_k + q;
            As[la_k + q][la_m] = (am < M && ak < K) ? A[(size_t)am * lda + ak] : 0.f;
        }
        int bk = k0 + lb_k;
        #pragma unroll
        for (int q = 0; q < 4; q++) {
            int bn = n0 + lb_n + q;
            Bs[lb_k][lb_n + q] = (bk < K && bn < N) ? B[(size_t)bk * ldb + bn] : 0.f;
        }
        __syncthreads();
        #pragma unroll
        for (int kk = 0; kk < 16; kk++) {
            float4 af = *(const float4*)&As[kk][ty << 2];
            ulonglong2 bt = *(const ulonglong2*)&Bs[kk][tx << 2];
            float a[4] = {af.x, af.y, af.z, af.w};
            #pragma unroll
            for (int r = 0; r < 4; r++) {
                ull ap = pk2(a[r]);
                fma2(acc2[r][0], ap, bt.x);
                fma2(acc2[r][1], ap, bt.y);
            }
        }
        __syncthreads();
    }

    #pragma unroll
    for (int r = 0; r < 4; r++) {
        int m = m0 + (ty << 2) + r;
        if (m >= M) continue;
        float av[4];
        unpk(acc2[r][0], av[0], av[1]);
        unpk(acc2[r][1], av[2], av[3]);
        #pragma unroll
        for (int c = 0; c < 4; c++) {
            int n = n0 + (tx << 2) + c;
            if (n >= N) continue;
            float v = av[c];
            if (bias) v += bias[n];
            if (dorelu) v = fmaxf(v, 0.f);
            C[(size_t)m * ldc + n] = v;
        }
    }
}

// ---------------- dual GEMM: U = A@(B1 - sub*B2), V = A@B2 (shared A tile) -------------
__global__ void __launch_bounds__(256)
gemm_uv_kernel(const float* __restrict__ A, int lda,
               const float* __restrict__ B1, const float* __restrict__ B2, int ldb,
               float* __restrict__ Uo, float* __restrict__ Vo, int ldu,
               int M, int N, int K, int sub) {
    __shared__ __align__(16) float As[16][68];
    __shared__ __align__(16) float B1s[16][68];
    __shared__ __align__(16) float B2s[16][68];
    int tid = threadIdx.x;
    int tx = tid & 15, ty = tid >> 4;
    int m0 = blockIdx.x * 64, n0 = blockIdx.y * 64;
    ull aU[4][2], aV[4][2];
    #pragma unroll
    for (int r = 0; r < 4; r++) {
        aU[r][0] = aU[r][1] = 0ull;
        aV[r][0] = aV[r][1] = 0ull;
    }

    int la_m = tid >> 2;
    int la_k = (tid & 3) << 2;
    int lb_k = tid >> 4;
    int lb_n = (tid & 15) << 2;

    for (int k0 = 0; k0 < K; k0 += 16) {
        int am = m0 + la_m;
        #pragma unroll
        for (int q = 0; q < 4; q++) {
            int ak = k0 + la_k + q;
            As[la_k + q][la_m] = (am < M && ak < K) ? A[(size_t)am * lda + ak] : 0.f;
        }
        int bk = k0 + lb_k;
        #pragma unroll
        for (int q = 0; q < 4; q++) {
            int bn = n0 + lb_n + q;
            float v1 = 0.f, v2 = 0.f;
            if (bk < K && bn < N) {
                size_t o = (size_t)bk * ldb + bn;
                v1 = B1[o]; v2 = B2[o];
            }
            B1s[lb_k][lb_n + q] = sub ? (v1 - v2) : v1;
            B2s[lb_k][lb_n + q] = v2;
        }
        __syncthreads();
        #pragma unroll
        for (int kk = 0; kk < 16; kk++) {
            float4 af = *(const float4*)&As[kk][ty << 2];
            ulonglong2 b1t = *(const ulonglong2*)&B1s[kk][tx << 2];
            ulonglong2 b2t = *(const ulonglong2*)&B2s[kk][tx << 2];
            float a[4] = {af.x, af.y, af.z, af.w};
            #pragma unroll
            for (int r = 0; r < 4; r++) {
                ull ap = pk2(a[r]);
                fma2(aU[r][0], ap, b1t.x);
                fma2(aU[r][1], ap, b1t.y);
                fma2(aV[r][0], ap, b2t.x);
                fma2(aV[r][1], ap, b2t.y);
            }
        }
        __syncthreads();
    }

    #pragma unroll
    for (int r = 0; r < 4; r++) {
        int m = m0 + (ty << 2) + r;
        if (m >= M) continue;
        float u[4], v[4];
        unpk(aU[r][0], u[0], u[1]); unpk(aU[r][1], u[2], u[3]);
        unpk(aV[r][0], v[0], v[1]); unpk(aV[r][1], v[2], v[3]);
        #pragma unroll
        for (int c = 0; c < 4; c++) {
            int n = n0 + (tx << 2) + c;
            if (n >= N) continue;
            Uo[(size_t)m * ldu + n] = u[c];
            Vo[(size_t)m * ldu + n] = v[c];
        }
    }
}

// ---------------- global max pool over N ----------------
__global__ void gmax_kernel() {
    int b = blockIdx.x, c = threadIdx.x;
    const float* p = g_sf + (size_t)b * NPTS * 128 + c;
    float m = -3.3e38f;
    #pragma unroll 4
    for (int n = 0; n < NPTS; n++) m = fmaxf(m, p[n * 128]);
    g_gmax[b * 128 + c] = m;
}

// ---------------- hg = g @ ec_w1[256:384] + ec_b1 ----------------
__global__ void hg_kernel(const float* __restrict__ w1, const float* __restrict__ b1) {
    int b = blockIdx.x, c = threadIdx.x;
    float s = b1[c];
    #pragma unroll 4
    for (int d = 0; d < 128; d++) s += g_gmax[b * 128 + d] * w1[(256 + d) * 128 + c];
    g_hg[b * 128 + c] = s;
}

// ---------------- pair kernel: 64x64 tile, 4x4 pairs/thread, fused relu+dot+sigmoid ----
__global__ void __launch_bounds__(256)
pair_kernel(const float* __restrict__ w2, const float* __restrict__ b2,
            float* __restrict__ out) {
    int bx = blockIdx.x, by = blockIdx.y;   // bx = j tile, by = i tile
    if (bx < by) return;
    int b = blockIdx.z;
    extern __shared__ float ps[];
    float* s_hi = ps;                 // 64 x 132
    float* s_hj = ps + 64 * 132;      // 64 x 132
    float* s_w  = ps + 2 * 64 * 132;  // 128

    int tid = threadIdx.y * 16 + threadIdx.x;
    int bi0 = by * 64, bj0 = bx * 64;

    for (int t = tid; t < 64 * 32; t += 256) {
        int r = t >> 5, c4 = (t & 31) << 2;
        int gi = bi0 + r;
        float4 v = make_float4(0.f, 0.f, 0.f, 0.f);
        if (gi < NPTS) v = *(const float4*)&g_hi[((size_t)(b * NPTS + gi)) * 128 + c4];
        *(float4*)&s_hi[r * 132 + c4] = v;
        int gj = bj0 + r;
        float4 u = make_float4(0.f, 0.f, 0.f, 0.f);
        if (gj < NPTS) {
            u = *(const float4*)&g_hjg[((size_t)(b * NPTS + gj)) * 128 + c4];
            float4 hgv = *(const float4*)&g_hg[b * 128 + c4];
            u.x += hgv.x; u.y += hgv.y; u.z += hgv.z; u.w += hgv.w;
        }
        *(float4*)&s_hj[r * 132 + c4] = u;
    }
    if (tid < 32) *(float4*)&s_w[tid * 4] = *(const float4*)&w2[tid * 4];
    __syncthreads();

    int ri0 = threadIdx.y * 4, cj0 = threadIdx.x * 4;
    float acc[4][4] = {};
    for (int c4 = 0; c4 < 128; c4 += 4) {
        float4 w = *(const float4*)&s_w[c4];
        float4 A[4], H[4];
        #pragma unroll
        for (int r = 0; r < 4; r++) A[r] = *(const float4*)&s_hi[(ri0 + r) * 132 + c4];
        #pragma unroll
        for (int c = 0; c < 4; c++) H[c] = *(const float4*)&s_hj[(cj0 + c) * 132 + c4];
        #pragma unroll
        for (int r = 0; r < 4; r++)
            #pragma unroll
            for (int c = 0; c < 4; c++) {
                acc[r][c] += fmaxf(A[r].x + H[c].x, 0.f) * w.x
                           + fmaxf(A[r].y + H[c].y, 0.f) * w.y
                           + fmaxf(A[r].z + H[c].z, 0.f) * w.z
                           + fmaxf(A[r].w + H[c].w, 0.f) * w.w;
            }
    }

    float bias2 = b2[0];
    #pragma unroll
    for (int r = 0; r < 4; r++) {
        int gi = bi0 + ri0 + r;
        #pragma unroll
        for (int c = 0; c < 4; c++) {
            int gj = bj0 + cj0 + c;
            if (gj < NPTS && gi < gj) {
                float m = acc[r][c] + bias2;
                int p = gi * (NPTS - 1) - (gi * (gi - 1)) / 2 + (gj - gi - 1);
                int off = b * NPAIR + p;
                out[off] = 1.f / (1.f + __expf(-m));
                out[BATCH * NPAIR + off] = m;
            }
        }
    }
}

// ============================ host side ============================
static void* sym_addr(const void* s) {
    void* p = nullptr;
    cudaGetSymbolAddress(&p, s);
    return p;
}

static void gemm(const float* A, int lda, const float* B, int ldb,
                 float* C, int ldc, int M, int N, int K,
                 const float* bias, int dorelu) {
    dim3 g((M + 63) / 64, (N + 63) / 64);
    gemm_kernel<<<g, 256>>>(A, lda, B, ldb, C, ldc, M, N, K, bias, dorelu);
}

static void edge_conv(const float* x, int lda, int C, int H, int H2,
                      const float* w1, const float* b1,
                      const float* w2, const float* b2,
                      float* U, float* V, float* G,
                      float* outp, int ldo) {
    xxt_kernel<<<dim3(8, 8, BATCH), 256>>>(x, lda, C, G);
    diag_kernel<<<(BNODES + 255) / 256, 256>>>(G);
    topk_kernel<<<BNODES, 128>>>(G);
    // U = x @ (w1[:C] - w1[C:]) ; V = x @ w1[C:]   (one dual-output launch)
    dim3 guv((BNODES + 63) / 64, (H + 63) / 64);
    gemm_uv_kernel<<<guv, 256>>>(x, lda, w1, w1 + (size_t)C * H, H,
                                 U, V, H, BNODES, H, C, 1);
    fused_edge_gemm<<<dim3(125, (H2 + 127) / 128), 256>>>(U, V, b1, w2, b2, outp, ldo, H, H2);
}

extern "C" void kernel_launch(void* const* d_in, const int* in_sizes, int n_in,
                              void* d_out, int out_size) {
    const float* in[21];
    for (int i = 0; i < 21; i++) in[i] = (const float*)d_in[i];
    const float* pos   = in[0];
    const float* c1_w1 = in[1];  const float* c1_b1 = in[2];
    const float* c1_w2 = in[3];  const float* c1_b2 = in[4];
    const float* c2_w1 = in[5];  const float* c2_b1 = in[6];
    const float* c2_w2 = in[7];  const float* c2_b2 = in[8];
    const float* c3_w1 = in[9];  const float* c3_b1 = in[10];
    const float* c3_w2 = in[11]; const float* c3_b2 = in[12];
    const float* sm_w1 = in[13]; const float* sm_b1 = in[14];
    const float* sm_w2 = in[15]; const float* sm_b2 = in[16];
    const float* ec_w1 = in[17]; const float* ec_b1 = in[18];
    const float* ec_w2 = in[19]; const float* ec_b2 = in[20];

    float* U   = (float*)sym_addr(g_U);
    float* V   = (float*)sym_addr(g_V);
    float* G   = (float*)sym_addr(g_G);
    float* cat = (float*)sym_addr(g_cat);
    float* smh = (float*)sym_addr(g_smh);
    float* sf  = (float*)sym_addr(g_sf);
    float* hi  = (float*)sym_addr(g_hi);
    float* hjg = (float*)sym_addr(g_hjg);

    // conv1: pos[2000,3] -> x1 at cat+0 (32 ch)
    edge_conv(pos, 3, 3, 16, 32, c1_w1, c1_b1, c1_w2, c1_b2, U, V, G, cat + 0, 672);
    // conv2: x1 -> x2 at cat+32 (128 ch)
    edge_conv(cat + 0, 672, 32, 64, 128, c2_w1, c2_b1, c2_w2, c2_b2, U, V, G, cat + 32, 672);
    // conv3: x2 -> x3 at cat+160 (512 ch)
    edge_conv(cat + 32, 672, 128, 256, 512, c3_w1, c3_b1, c3_w2, c3_b2, U, V, G, cat + 160, 672);

    // sm MLP: [2000,672] -> relu 256 -> 128
    gemm(cat, 672, sm_w1, 256, smh, 256, BNODES, 256, 672, sm_b1, 1);
    gemm(smh, 256, sm_w2, 128, sf, 128, BNODES, 128, 256, sm_b2, 0);

    // global max pool
    gmax_kernel<<<BATCH, 128>>>();

    // hi = sf @ ec_w1[:128]; hjg = sf @ ec_w1[128:256]  (one dual launch, no subtraction)
    dim3 ghh((BNODES + 63) / 64, 2);
    gemm_uv_kernel<<<ghh, 256>>>(sf, 128, ec_w1 + 128 * 128, ec_w1, 128,
                                 hjg, hi, 128, BNODES, 128, 128, 0);
    // note: V-output = A@B2 = sf@ec_w1[:128] -> hi ; U-output (sub=0) = sf@B1 -> hjg
    hg_kernel<<<BATCH, 128>>>(ec_w1, ec_b1);

    // fused pair stage -> d_out = [pair_prob (B*P), mlp_out (B*P)]
    size_t psmem = (2 * 64 * 132 + 128) * sizeof(float);
    cudaFuncSetAttribute(pair_kernel, cudaFuncAttributeMaxDynamicSharedMemorySize, (int)psmem);
    pair_kernel<<<dim3(16, 16, BATCH), dim3(16, 16), psmem>>>(ec_w2, ec_b2, (float*)d_out);
}